// round 13
// baseline (speedup 1.0000x reference)
#include <cuda_runtime.h>
#include <cstdint>

// Correlation via parity-split banded GEMM on mma.sync (tf32, m16n8k8).
// out[b, i*41+j, y, x] = (1/576) * sum_c in1[b,c,y,x] * in2[b,c,y-2(j-10),x-2(i-10)]
// Parity split: x=2u+p, x2=2v+p, v-u = 10-i in [-30,10].
// Per (b,y,j,p): G_p[u,v] = sum_c A_p[u,c] B_p[v,c];  out[i,2u+p] = G_p[u,u+10-i].
// Single-sync pipelined loop: gather(j-1) and prefetch B(j+1) overlap MMA(j).

#define W     160
#define H     96
#define CC    64
#define NB    4
#define ND    41
#define CROW  (H*W)
#define ROWSZ 10240          // floats per transposed (b,y) block: 160 rows x 64 c

#define THREADS 320          // 10 warps: (parity, mtile)
#define PAD     68           // smem row pitch (floats) for A/B
#define BROWS   96           // B rows per parity: margin 8 + 80 + margin 8
#define BMARG   8
#define BBUF    13056        // 2*96*68 floats per B buffer
#define SPITCH  57           // stripe row pitch
#define SBUF    9120         // 2*5*16*57 floats per stripe buffer

// dynamic smem float offsets
#define FA 0                                     // 2*80*68  = 10880
#define FB 10880                                 // 2*13056  = 26112
#define FS 36992                                 // 2*9120   = 18240
#define SMEM_FLOATS 55232
#define SMEM_BYTES  (SMEM_FLOATS * 4)            // 220928 B

__device__ uint32_t g_in1T[NB * H * ROWSZ];
__device__ uint32_t g_in2T[NB * H * ROWSZ];

__device__ __forceinline__ uint32_t cvt_tf32(float f) {
    uint32_t r;
    asm("cvt.rna.tf32.f32 %0, %1;" : "=r"(r) : "f"(f));
    return r;
}

__device__ __forceinline__ void cp16(uint32_t sdst, const void* src) {
    asm volatile("cp.async.cg.shared.global [%0], [%1], 16;\n" :: "r"(sdst), "l"(src));
}
__device__ __forceinline__ void cp_commit() { asm volatile("cp.async.commit_group;\n" ::); }
template <int N> __device__ __forceinline__ void cp_wait() {
    asm volatile("cp.async.wait_group %0;\n" :: "n"(N));
}

__device__ __forceinline__ void mma_tf32(float* d, const uint32_t* a, const uint32_t* b) {
    asm volatile(
        "mma.sync.aligned.m16n8k8.row.col.f32.tf32.tf32.f32 "
        "{%0,%1,%2,%3}, {%4,%5,%6,%7}, {%8,%9}, {%0,%1,%2,%3};"
        : "+f"(d[0]), "+f"(d[1]), "+f"(d[2]), "+f"(d[3])
        : "r"(a[0]), "r"(a[1]), "r"(a[2]), "r"(a[3]), "r"(b[0]), "r"(b[1]));
}

// ---------- pre-pass: per (b,y), transpose both inputs to [p*80+u][c] tf32 rows ----------
__global__ __launch_bounds__(256)
void prepass(const float* __restrict__ in1, const float* __restrict__ in2) {
    __shared__ uint32_t stag[160 * PAD];
    const int y = blockIdx.x, b = blockIdx.y, t = threadIdx.x;
    for (int s = 0; s < 2; s++) {
        const float* src = (s ? in2 : in1) + ((size_t)(b * CC) * H + y) * W;
        uint32_t* dst = (s ? g_in2T : g_in1T) + (size_t)(b * H + y) * ROWSZ;
        if (s) __syncthreads();
        for (int idx = t; idx < ROWSZ; idx += 256) {
            int c = idx / W;
            int xx = idx - c * W;
            int r = (xx & 1) * 80 + (xx >> 1);
            stag[r * PAD + c] = cvt_tf32(src[(size_t)c * CROW + xx]);
        }
        __syncthreads();
        for (int k = t; k < ROWSZ / 4; k += 256) {
            int row = k >> 4, q = k & 15;
            ((uint4*)dst)[k] = *(const uint4*)&stag[row * PAD + q * 4];
        }
        __syncthreads();
    }
}

// diagonal gather + coalesced store for one finished j
__device__ __forceinline__ void do_gather(const float* __restrict__ sm, int sbuf,
                                          float* __restrict__ obase, int t,
                                          size_t ostride_i, float scale) {
    const float* stripe = sm + FS + sbuf * SBUF;
    for (int idx = t; idx < ND * 40; idx += THREADS) {
        int i = idx / 40, q = idx - i * 40;
        float4 v4;
        float* vv = (float*)&v4;
#pragma unroll
        for (int e = 0; e < 4; e++) {
            int x = 4 * q + e;
            int pp = x & 1, u = x >> 1;
            int v = u + 10 - i;
            float val = 0.f;
            if ((unsigned)v < 80u) {
                int mtt = u >> 4;
                val = stripe[((pp * 5 + mtt) * 16 + (u & 15)) * SPITCH
                             + (v - 16 * mtt + 30)] * scale;
            }
            vv[e] = val;
        }
        *(float4*)(obase + (size_t)i * ostride_i + 4 * q) = v4;
    }
}

// ---------- main kernel: block = (jh, y, b) ----------
__global__ __launch_bounds__(THREADS, 1)
void corr_main(float* __restrict__ out) {
    extern __shared__ float sm[];
    const int jh = blockIdx.x, y = blockIdx.y, b = blockIdx.z;
    const int t = threadIdx.x, wid = t >> 5, lane = t & 31;
    const int g = lane >> 2, tig = lane & 3;

    const int j0 = jh * 21, jcnt = jh ? 20 : 21;
    const size_t ostride_i = (size_t)ND * H * W;
    const float scale = 1.0f / 576.0f;

    uint32_t sb;
    { unsigned long long gg = __cvta_generic_to_shared(sm); sb = (uint32_t)gg; }

    // enumerate valid j; zero-fill invalid j slabs
    int jv[21], y2v[21], nvalid = 0;
    for (int jj = 0; jj < jcnt; jj++) {
        int j = j0 + jj;
        int y2 = y - 2 * (j - 10);
        if (y2 >= 0 && y2 < H) { jv[nvalid] = j; y2v[nvalid] = y2; nvalid++; }
        else {
            float* base = out + (((size_t)(b * ND * ND + j)) * H + y) * W;
            for (int idx = t; idx < ND * (W / 4); idx += THREADS) {
                int i = idx / (W / 4), q = idx - i * (W / 4);
                ((float4*)(base + (size_t)i * ostride_i))[q] = make_float4(0.f, 0.f, 0.f, 0.f);
            }
        }
    }
    if (nvalid == 0) return;

    // stage A (once) + B(0) into buf0
    {
        const uint32_t* A = g_in1T + (size_t)(b * H + y) * ROWSZ;
        const uint32_t* B = g_in2T + (size_t)(b * H + y2v[0]) * ROWSZ;
        for (int k = t; k < 2560; k += THREADS) {          // 160 rows x 16 chunks
            int row = k >> 4, q = k & 15;                  // row = p*80+u
            int p = row >= 80, u = row - p * 80;
            cp16(sb + (FA + row * PAD + q * 4) * 4, A + row * 64 + q * 4);
            int brow = p * BROWS + BMARG + u;
            cp16(sb + (FB + brow * PAD + q * 4) * 4, B + row * 64 + q * 4);
        }
        cp_commit();
    }

    const int p  = wid / 5;          // parity
    const int mt = wid - p * 5;      // m-tile
    const int u0 = 16 * mt;
    // n-tile band clamp (skip tiles with no column in [0,80))
    const int ntlo_t[5] = {3, 1, 0, 0, 0};
    const int nthi_t[5] = {6, 6, 6, 6, 5};
    const int ntlo = ntlo_t[mt], nthi = nthi_t[mt];

    for (int n = 0; n < nvalid; n++) {
        const int buf = n & 1;
        cp_wait<0>();          // B(n) complete (issued last iter / pre-loop)
        __syncthreads();       // publishes B(n); stripe[buf] free; stripe[buf^1] complete

        // prefetch B(n+1) into buf^1 (safe: MMA(n-1) reads of buf^1 are behind the sync)
        if (n + 1 < nvalid) {
            const uint32_t* B = g_in2T + (size_t)(b * H + y2v[n + 1]) * ROWSZ;
            const int fb = FB + (buf ^ 1) * BBUF;
            for (int k = t; k < 2560; k += THREADS) {
                int row = k >> 4, q = k & 15;
                int pp = row >= 80, u = row - pp * 80;
                int brow = pp * BROWS + BMARG + u;
                cp16(sb + (fb + brow * PAD + q * 4) * 4, B + row * 64 + q * 4);
            }
            cp_commit();
        }

        // gather previous j (reads stripe[buf^1]); STG drains under the MMA below
        if (n > 0) {
            float* obase = out + (((size_t)(b * ND * ND + jv[n - 1])) * H + y) * W;
            do_gather(sm, buf ^ 1, obase, t, ostride_i, scale);
        }

        // ---- banded MMA: this warp = (p, mt); n-tiles [ntlo,nthi] x 8 k-steps ----
        float acc[7][4];
#pragma unroll
        for (int nt = 0; nt < 7; nt++)
#pragma unroll
            for (int e = 0; e < 4; e++) acc[nt][e] = 0.f;

        const uint32_t* Ab = (const uint32_t*)&sm[FA + (p * 80 + u0 + g) * PAD + tig];
        // B row for v stored at p*BROWS + BMARG + v; nt reads v = u0-30+8nt+g
        const uint32_t* Bb = (const uint32_t*)&sm[FB + buf * BBUF
                             + (p * BROWS + BMARG + u0 - 30 + g) * PAD + tig];
#pragma unroll
        for (int kk = 0; kk < 8; kk++) {
            const int c0 = 8 * kk;
            uint32_t a[4];
            a[0] = Ab[c0];
            a[1] = Ab[c0 + 8 * PAD];
            a[2] = Ab[c0 + 4];
            a[3] = Ab[c0 + 8 * PAD + 4];
#pragma unroll
            for (int nt = 0; nt < 7; nt++) {
                if (nt < ntlo || nt > nthi) continue;   // warp-uniform skip
                uint32_t bfrag[2];
                const uint32_t* bp = Bb + 8 * nt * PAD + c0;
                bfrag[0] = bp[0];
                bfrag[1] = bp[4];
                mma_tf32(acc[nt], a, bfrag);
            }
        }

        // ---- store band to stripe[buf] (read by gather in iter n+1 after its sync) ----
        {
            float* s0 = &sm[FS + buf * SBUF + ((p * 5 + mt) * 16 + g) * SPITCH + 2 * tig];
            float* s1 = s0 + 8 * SPITCH;
#pragma unroll
            for (int nt = 0; nt < 7; nt++) {
                s0[8 * nt]     = acc[nt][0];
                s0[8 * nt + 1] = acc[nt][1];
                s1[8 * nt]     = acc[nt][2];
                s1[8 * nt + 1] = acc[nt][3];
            }
        }
    }

    // final gather
    __syncthreads();
    {
        const int n = nvalid - 1;
        float* obase = out + (((size_t)(b * ND * ND + jv[n])) * H + y) * W;
        do_gather(sm, n & 1, obase, t, ostride_i, scale);
    }
}

extern "C" void kernel_launch(void* const* d_in, const int* in_sizes, int n_in,
                              void* d_out, int out_size) {
    const float* in1 = (const float*)d_in[0];
    const float* in2 = (const float*)d_in[1];
    cudaFuncSetAttribute(corr_main, cudaFuncAttributeMaxDynamicSharedMemorySize, SMEM_BYTES);
    prepass<<<dim3(H, NB), 256>>>(in1, in2);
    corr_main<<<dim3(2, H, NB), THREADS, SMEM_BYTES>>>((float*)d_out);
}

// round 16
// speedup vs baseline: 1.0463x; 1.0463x over previous
#include <cuda_runtime.h>
#include <cstdint>

// Correlation via parity-split banded GEMM on mma.sync (tf32, m16n8k8).
// out[b, i*41+j, y, x] = (1/576) * sum_c in1[b,c,y,x] * in2[b,c,y-2(j-10),x-2(i-10)]
// Parity split: x=2u+p, x2=2v+p, v-u = 10-i in [-30,10].
// Per (b,y,j,p): G_p[u,v] = sum_c A_p[u,c] B_p[v,c];  out[i,2u+p] = G_p[u,u+10-i].
// 20 warps: each (parity, mtile) pair split across 2 warps by K-half;
// two stripe banks summed in the gather.

#define W     160
#define H     96
#define CC    64
#define NB    4
#define ND    41
#define CROW  (H*W)
#define ROWSZ 10240          // floats per transposed (b,y) block: 160 rows x 64 c

#define THREADS 640          // 20 warps: (parity, mtile, khalf)
#define PAD     68           // smem row pitch (floats) for A/B
#define BROWS   96           // B rows per parity: margin 8 + 80 + margin 8
#define BMARG   8
#define BBUF    13056        // 2*96*68 floats per B buffer
#define SPITCH  57           // stripe row pitch
#define SBUF    9120         // 2*5*16*57 floats per stripe bank

// dynamic smem float offsets
#define FA 0                                     // 2*80*68  = 10880
#define FB 10880                                 // 2*13056  = 26112
#define FS 36992                                 // 2*9120   = 18240 (kh banks)
#define SMEM_FLOATS 55232
#define SMEM_BYTES  (SMEM_FLOATS * 4)            // 220928 B

__device__ uint32_t g_in1T[NB * H * ROWSZ];
__device__ uint32_t g_in2T[NB * H * ROWSZ];

__device__ __forceinline__ uint32_t cvt_tf32(float f) {
    uint32_t r;
    asm("cvt.rna.tf32.f32 %0, %1;" : "=r"(r) : "f"(f));
    return r;
}

__device__ __forceinline__ void cp16(uint32_t sdst, const void* src) {
    asm volatile("cp.async.cg.shared.global [%0], [%1], 16;\n" :: "r"(sdst), "l"(src));
}
__device__ __forceinline__ void cp_commit() { asm volatile("cp.async.commit_group;\n" ::); }
template <int N> __device__ __forceinline__ void cp_wait() {
    asm volatile("cp.async.wait_group %0;\n" :: "n"(N));
}

__device__ __forceinline__ void mma_tf32(float* d, const uint32_t* a, const uint32_t* b) {
    asm volatile(
        "mma.sync.aligned.m16n8k8.row.col.f32.tf32.tf32.f32 "
        "{%0,%1,%2,%3}, {%4,%5,%6,%7}, {%8,%9}, {%0,%1,%2,%3};"
        : "+f"(d[0]), "+f"(d[1]), "+f"(d[2]), "+f"(d[3])
        : "r"(a[0]), "r"(a[1]), "r"(a[2]), "r"(a[3]), "r"(b[0]), "r"(b[1]));
}

// ---------- pre-pass: per (b,y), transpose both inputs to [p*80+u][c] tf32 rows ----------
__global__ __launch_bounds__(256)
void prepass(const float* __restrict__ in1, const float* __restrict__ in2) {
    __shared__ uint32_t stag[160 * PAD];
    const int y = blockIdx.x, b = blockIdx.y, t = threadIdx.x;
    for (int s = 0; s < 2; s++) {
        const float* src = (s ? in2 : in1) + ((size_t)(b * CC) * H + y) * W;
        uint32_t* dst = (s ? g_in2T : g_in1T) + (size_t)(b * H + y) * ROWSZ;
        if (s) __syncthreads();
        for (int idx = t; idx < ROWSZ; idx += 256) {
            int c = idx / W;
            int xx = idx - c * W;
            int r = (xx & 1) * 80 + (xx >> 1);
            stag[r * PAD + c] = cvt_tf32(src[(size_t)c * CROW + xx]);
        }
        __syncthreads();
        for (int k = t; k < ROWSZ / 4; k += 256) {
            int row = k >> 4, q = k & 15;
            ((uint4*)dst)[k] = *(const uint4*)&stag[row * PAD + q * 4];
        }
        __syncthreads();
    }
}

// diagonal gather (sums the two K-half stripe banks) + coalesced store
__device__ __forceinline__ void do_gather(const float* __restrict__ sm,
                                          float* __restrict__ obase, int t,
                                          size_t ostride_i, float scale) {
    for (int idx = t; idx < ND * 40; idx += THREADS) {
        int i = idx / 40, q = idx - i * 40;
        float4 v4;
        float* vv = (float*)&v4;
#pragma unroll
        for (int e = 0; e < 4; e++) {
            int x = 4 * q + e;
            int pp = x & 1, u = x >> 1;
            int v = u + 10 - i;
            float val = 0.f;
            if ((unsigned)v < 80u) {
                int mtt = u >> 4;
                int si = ((pp * 5 + mtt) * 16 + (u & 15)) * SPITCH + (v - 16 * mtt + 30);
                val = (sm[FS + si] + sm[FS + SBUF + si]) * scale;
            }
            vv[e] = val;
        }
        *(float4*)(obase + (size_t)i * ostride_i + 4 * q) = v4;
    }
}

// ---------- main kernel: block = (jh, y, b) ----------
__global__ __launch_bounds__(THREADS, 1)
void corr_main(float* __restrict__ out) {
    extern __shared__ float sm[];
    const int jh = blockIdx.x, y = blockIdx.y, b = blockIdx.z;
    const int t = threadIdx.x, wid = t >> 5, lane = t & 31;
    const int g = lane >> 2, tig = lane & 3;

    const int j0 = jh * 21, jcnt = jh ? 20 : 21;
    const size_t ostride_i = (size_t)ND * H * W;
    const float scale = 1.0f / 576.0f;

    uint32_t sb;
    { unsigned long long gg = __cvta_generic_to_shared(sm); sb = (uint32_t)gg; }

    // enumerate valid j; zero-fill invalid j slabs
    int jv[21], y2v[21], nvalid = 0;
    for (int jj = 0; jj < jcnt; jj++) {
        int j = j0 + jj;
        int y2 = y - 2 * (j - 10);
        if (y2 >= 0 && y2 < H) { jv[nvalid] = j; y2v[nvalid] = y2; nvalid++; }
        else {
            float* base = out + (((size_t)(b * ND * ND + j)) * H + y) * W;
            for (int idx = t; idx < ND * (W / 4); idx += THREADS) {
                int i = idx / (W / 4), q = idx - i * (W / 4);
                ((float4*)(base + (size_t)i * ostride_i))[q] = make_float4(0.f, 0.f, 0.f, 0.f);
            }
        }
    }
    if (nvalid == 0) return;

    // stage A (once) + B(0) into buf0
    {
        const uint32_t* A = g_in1T + (size_t)(b * H + y) * ROWSZ;
        const uint32_t* B = g_in2T + (size_t)(b * H + y2v[0]) * ROWSZ;
        for (int k = t; k < 2560; k += THREADS) {          // 160 rows x 16 chunks
            int row = k >> 4, q = k & 15;                  // row = p*80+u
            int p = row >= 80, u = row - p * 80;
            cp16(sb + (FA + row * PAD + q * 4) * 4, A + row * 64 + q * 4);
            int brow = p * BROWS + BMARG + u;
            cp16(sb + (FB + brow * PAD + q * 4) * 4, B + row * 64 + q * 4);
        }
        cp_commit();
    }

    // warp role: p = parity, mt = m-tile, kh = K-half
    const int p  = wid / 10;
    const int r10 = wid - p * 10;
    const int mt = r10 >> 1;
    const int kh = r10 & 1;
    const int u0 = 16 * mt;
    const int c0base = 32 * kh;

    // A and B never move for this warp; precompute fragment base pointers
    const uint32_t* Ab = (const uint32_t*)&sm[FA + (p * 80 + u0 + g) * PAD + tig];
    const int bb_row = (p * BROWS + BMARG + u0 - 30 + g) * PAD + tig;

    cp_wait<0>();
    __syncthreads();            // A + B(0) visible to all warps

    // hoist A fragments: 4 k-steps x 4 regs (A is j-invariant)
    uint32_t afr[4][4];
#pragma unroll
    for (int kko = 0; kko < 4; kko++) {
        const int c0 = c0base + 8 * kko;
        afr[kko][0] = Ab[c0];
        afr[kko][1] = Ab[c0 + 8 * PAD];
        afr[kko][2] = Ab[c0 + 4];
        afr[kko][3] = Ab[c0 + 8 * PAD + 4];
    }

    for (int n = 0; n < nvalid; n++) {
        const int buf = n & 1;
        // prefetch B(n+1) into buf^1 (MMA(n-1) reads of buf^1 finished before
        // iter n-1's second sync, which precedes this point for all threads)
        if (n + 1 < nvalid) {
            const uint32_t* B = g_in2T + (size_t)(b * H + y2v[n + 1]) * ROWSZ;
            const int fb = FB + (buf ^ 1) * BBUF;
            for (int k = t; k < 2560; k += THREADS) {
                int row = k >> 4, q = k & 15;
                int pp = row >= 80, u = row - pp * 80;
                int brow = pp * BROWS + BMARG + u;
                cp16(sb + (fb + brow * PAD + q * 4) * 4, B + row * 64 + q * 4);
            }
            cp_commit();
            cp_wait<1>();       // B(n) complete; B(n+1) still in flight
        } else {
            cp_wait<0>();
        }
        __syncthreads();        // publishes B(n); gather(n-1) stripe reads done

        // ---- banded MMA: this warp = (p, mt, kh); 7 n-tiles x 4 k-steps ----
        float acc[7][4];
#pragma unroll
        for (int nt = 0; nt < 7; nt++)
#pragma unroll
            for (int e = 0; e < 4; e++) acc[nt][e] = 0.f;

        const uint32_t* Bb = (const uint32_t*)&sm[FB + buf * BBUF + bb_row];
#pragma unroll
        for (int kko = 0; kko < 4; kko++) {
            const int c0 = c0base + 8 * kko;
#pragma unroll
            for (int nt = 0; nt < 7; nt++) {
                uint32_t bfrag[2];
                const uint32_t* bp = Bb + 8 * nt * PAD + c0;
                bfrag[0] = bp[0];
                bfrag[1] = bp[4];
                mma_tf32(acc[nt], afr[kko], bfrag);
            }
        }

        // ---- store band to this K-half's stripe bank ----
        {
            float* s0 = &sm[FS + kh * SBUF + ((p * 5 + mt) * 16 + g) * SPITCH + 2 * tig];
            float* s1 = s0 + 8 * SPITCH;
#pragma unroll
            for (int nt = 0; nt < 7; nt++) {
                s0[8 * nt]     = acc[nt][0];
                s0[8 * nt + 1] = acc[nt][1];
                s1[8 * nt]     = acc[nt][2];
                s1[8 * nt + 1] = acc[nt][3];
            }
        }
        __syncthreads();        // stripe complete

        // ---- diagonal gather + coalesced store (STG drains under next prefetch/MMA) ----
        {
            float* obase = out + (((size_t)(b * ND * ND + jv[n])) * H + y) * W;
            do_gather(sm, obase, t, ostride_i, scale);
        }
    }
}

extern "C" void kernel_launch(void* const* d_in, const int* in_sizes, int n_in,
                              void* d_out, int out_size) {
    const float* in1 = (const float*)d_in[0];
    const float* in2 = (const float*)d_in[1];
    cudaFuncSetAttribute(corr_main, cudaFuncAttributeMaxDynamicSharedMemorySize, SMEM_BYTES);
    prepass<<<dim3(H, NB), 256>>>(in1, in2);
    corr_main<<<dim3(2, H, NB), THREADS, SMEM_BYTES>>>((float*)d_out);
}